// round 6
// baseline (speedup 1.0000x reference)
#include <cuda_runtime.h>
#include <math.h>

#define DTSTEP 0.03125f

// Scratch: voxel-major float4 volume. B=2, D=128 -> 2*128^3 float4 = 64 Mi bytes.
#define VOL4_CAP (2 * 128 * 128 * 128)
__device__ float4 g_vol4[VOL4_CAP];

// ---------------------------------------------------------------------------
// Pass 1: permute [B,4,D,D,D] channel-major -> [B,D,D,D] float4 voxel-major
// ---------------------------------------------------------------------------
__global__ void permute_kernel(const float* __restrict__ vol, int B, int D3) {
    int i = blockIdx.x * blockDim.x + threadIdx.x;
    int n = B * D3;
    if (i >= n) return;
    int b = i / D3;
    int r = i - b * D3;
    const float* base = vol + (size_t)b * 4 * D3 + r;
    g_vol4[i] = make_float4(base[0], base[(size_t)D3],
                            base[2 * (size_t)D3], base[3 * (size_t)D3]);
}

__device__ __forceinline__ float4 lerp4(float4 a, float4 b, float t) {
    float s = 1.0f - t;
    return make_float4(a.x * s + b.x * t,
                       a.y * s + b.y * t,
                       a.z * s + b.z * t,
                       a.w * s + b.w * t);
}

// ---------------------------------------------------------------------------
// Pass 2: one thread per pixel ray.
// All arithmetic feeding the in-box validity decision uses IEEE RN intrinsics
// to bit-match XLA (which emits separate non-contracted mul/add/div/sqrt HLO
// ops). Interpolation/compositing may use contracted FMA (ulp-level only).
// ---------------------------------------------------------------------------
__global__ void __launch_bounds__(256)
raymarch_kernel(const float* __restrict__ camrot,
                const float* __restrict__ campos,
                const float* __restrict__ focal,
                const float* __restrict__ princpt,
                const float* __restrict__ pix,
                const float* __restrict__ volraw,  // fallback path
                float* __restrict__ out,
                int B, int H, int W, int D, int nsteps, int use4) {
    int x = blockIdx.x * blockDim.x + threadIdx.x;
    int y = blockIdx.y * blockDim.y + threadIdx.y;
    int b = blockIdx.z;
    if (x >= W || y >= H) return;

    // --- camera ray (IEEE ops, mirroring XLA's separate HLO mul/add/div) ---
    float fx = focal[b * 2 + 0], fy = focal[b * 2 + 1];
    float px = princpt[b * 2 + 0], py = princpt[b * 2 + 1];
    size_t pidx = (((size_t)b * H + y) * W + x) * 2;
    float u = __fdiv_rn(__fsub_rn(pix[pidx + 0], px), fx);
    float v = __fdiv_rn(__fsub_rn(pix[pidx + 1], py), fy);

    const float* R = camrot + b * 9;
    // dir_j = sum_i R[i][j] * ray_i  (camrot^T applied), ray = (u, v, 1)
    // reduce order i = 0,1,2 to match XLA reduce
    float dx = __fadd_rn(__fadd_rn(__fmul_rn(R[0], u), __fmul_rn(R[3], v)), R[6]);
    float dy = __fadd_rn(__fadd_rn(__fmul_rn(R[1], u), __fmul_rn(R[4], v)), R[7]);
    float dz = __fadd_rn(__fadd_rn(__fmul_rn(R[2], u), __fmul_rn(R[5], v)), R[8]);

    // norm = sqrt((dx^2 + dy^2) + dz^2), each square rounded separately (no FMA)
    float sx = __fmul_rn(dx, dx);
    float sy = __fmul_rn(dy, dy);
    float sz = __fmul_rn(dz, dz);
    float norm = __fsqrt_rn(__fadd_rn(__fadd_rn(sx, sy), sz));
    dx = __fdiv_rn(dx, norm);
    dy = __fdiv_rn(dy, norm);
    dz = __fdiv_rn(dz, norm);

    float cx = campos[b * 3 + 0], cy = campos[b * 3 + 1], cz = campos[b * 3 + 2];

    // --- ray-AABB with [-1,1]^3 (IEEE division) ---
    float t1x = __fdiv_rn(__fsub_rn(-1.0f, cx), dx);
    float t2x = __fdiv_rn(__fsub_rn( 1.0f, cx), dx);
    float t1y = __fdiv_rn(__fsub_rn(-1.0f, cy), dy);
    float t2y = __fdiv_rn(__fsub_rn( 1.0f, cy), dy);
    float t1z = __fdiv_rn(__fsub_rn(-1.0f, cz), dz);
    float t2z = __fdiv_rn(__fsub_rn( 1.0f, cz), dz);
    float tmin = fmaxf(fminf(t1x, t2x),
                 fmaxf(fminf(t1y, t2y), fminf(t1z, t2z)));
    float tmax = fminf(fmaxf(t1x, t2x),
                 fminf(fmaxf(t1y, t2y), fmaxf(t1z, t2z)));
    bool hit = tmin < tmax;

    size_t obase = ((size_t)b * 4) * H * W + (size_t)y * W + x;
    size_t cstr = (size_t)H * W;

    if (!hit) {
        out[obase + 0 * cstr] = 0.0f;
        out[obase + 1 * cstr] = 0.0f;
        out[obase + 2 * cstr] = 0.0f;
        out[obase + 3 * cstr] = 0.0f;
        return;
    }

    float t0 = fmaxf(tmin, 0.0f);
    // raypos0 = campos + raydir * t0  (separate mul then add, no FMA)
    float posx = __fadd_rn(cx, __fmul_rn(dx, t0));
    float posy = __fadd_rn(cy, __fmul_rn(dy, t0));
    float posz = __fadd_rn(cz, __fmul_rn(dz, t0));

    // step = raydir * DT is EXACT (DT = 2^-5), so only the add rounds
    float stepx = __fmul_rn(dx, DTSTEP);
    float stepy = __fmul_rn(dy, DTSTEP);
    float stepz = __fmul_rn(dz, DTSTEP);

    float r0 = 0.0f, r1 = 0.0f, r2 = 0.0f, alpha = 0.0f;
    bool was_inside = false;

    const float hi = (float)(D - 1);
    const int D2 = D * D;
    const size_t vb = (size_t)b * D * D2;

    for (int s = 0; s < nsteps; ++s) {
        bool valid = (posx > -1.0f) & (posx < 1.0f) &
                     (posy > -1.0f) & (posy < 1.0f) &
                     (posz > -1.0f) & (posz < 1.0f);
        if (valid) {
            was_inside = true;
            // grid = clip(((pos+1)*0.5)*(D-1), 0, D-1); *0.5 is exact
            float gx = fminf(fmaxf(__fmul_rn(__fmul_rn(__fadd_rn(posx, 1.0f), 0.5f), hi), 0.0f), hi);
            float gy = fminf(fmaxf(__fmul_rn(__fmul_rn(__fadd_rn(posy, 1.0f), 0.5f), hi), 0.0f), hi);
            float gz = fminf(fmaxf(__fmul_rn(__fmul_rn(__fadd_rn(posz, 1.0f), 0.5f), hi), 0.0f), hi);
            int x0 = min((int)gx, D - 2);
            int y0 = min((int)gy, D - 2);
            int z0 = min((int)gz, D - 2);
            float wx = gx - (float)x0;
            float wy = gy - (float)y0;
            float wz = gz - (float)z0;

            float4 smp;
            if (use4) {
                size_t base = vb + (size_t)z0 * D2 + (size_t)y0 * D + x0;
                float4 c000 = g_vol4[base];
                float4 c001 = g_vol4[base + 1];
                float4 c010 = g_vol4[base + D];
                float4 c011 = g_vol4[base + D + 1];
                float4 c100 = g_vol4[base + D2];
                float4 c101 = g_vol4[base + D2 + 1];
                float4 c110 = g_vol4[base + D2 + D];
                float4 c111 = g_vol4[base + D2 + D + 1];
                float4 c00 = lerp4(c000, c001, wx);
                float4 c01 = lerp4(c010, c011, wx);
                float4 c10 = lerp4(c100, c101, wx);
                float4 c11 = lerp4(c110, c111, wx);
                float4 c0 = lerp4(c00, c01, wy);
                float4 c1 = lerp4(c10, c11, wy);
                smp = lerp4(c0, c1, wz);
            } else {
                size_t cstride = (size_t)D * D2;
                size_t base = (size_t)b * 4 * cstride + (size_t)z0 * D2 + (size_t)y0 * D + x0;
                float acc[4];
                #pragma unroll
                for (int c = 0; c < 4; ++c) {
                    const float* p = volraw + base + c * cstride;
                    float a00 = p[0]       * (1.0f - wx) + p[1]          * wx;
                    float a01 = p[D]       * (1.0f - wx) + p[D + 1]      * wx;
                    float a10 = p[D2]      * (1.0f - wx) + p[D2 + 1]     * wx;
                    float a11 = p[D2 + D]  * (1.0f - wx) + p[D2 + D + 1] * wx;
                    float a0 = a00 * (1.0f - wy) + a01 * wy;
                    float a1 = a10 * (1.0f - wy) + a11 * wy;
                    acc[c] = a0 * (1.0f - wz) + a1 * wz;
                }
                smp = make_float4(acc[0], acc[1], acc[2], acc[3]);
            }

            float contrib = fminf(alpha + smp.w * DTSTEP, 1.0f) - alpha;
            r0 += smp.x * contrib;
            r1 += smp.y * contrib;
            r2 += smp.z * contrib;
            alpha += contrib;
            if (1.0f - alpha < 1e-6f) break;   // remaining contribs bounded by 1e-6
        } else if (was_inside) {
            break;  // convex box: once exited, never valid again
        }
        // raypos = raypos + (raydir*DT); the product is exact, add is IEEE RN
        posx = __fadd_rn(posx, stepx);
        posy = __fadd_rn(posy, stepy);
        posz = __fadd_rn(posz, stepz);
    }

    out[obase + 0 * cstr] = r0;
    out[obase + 1 * cstr] = r1;
    out[obase + 2 * cstr] = r2;
    out[obase + 3 * cstr] = alpha;
}

// ---------------------------------------------------------------------------
// Launch
// ---------------------------------------------------------------------------
extern "C" void kernel_launch(void* const* d_in, const int* in_sizes, int n_in,
                              void* d_out, int out_size) {
    const float* camrot  = (const float*)d_in[0];
    const float* campos  = (const float*)d_in[1];
    const float* focal   = (const float*)d_in[2];
    const float* princpt = (const float*)d_in[3];
    const float* pix     = (const float*)d_in[4];
    const float* volume  = (const float*)d_in[5];
    float* out = (float*)d_out;

    int B = in_sizes[1] / 3;
    int hw = in_sizes[4] / (2 * B);
    int H = (int)(sqrt((double)hw) + 0.5);
    int W = H;
    int d3 = in_sizes[5] / (4 * B);
    int D = (int)(cbrt((double)d3) + 0.5);
    int nsteps = (int)ceil(2.0 * sqrt(3.0) / 0.03125);  // 111

    int use4 = (B * d3 <= VOL4_CAP) ? 1 : 0;
    if (use4) {
        int n = B * d3;
        permute_kernel<<<(n + 255) / 256, 256>>>(volume, B, d3);
    }

    dim3 block(32, 8, 1);
    dim3 grid((W + 31) / 32, (H + 7) / 8, B);
    raymarch_kernel<<<grid, block>>>(camrot, campos, focal, princpt, pix,
                                     volume, out, B, H, W, D, nsteps, use4);
}

// round 11
// speedup vs baseline: 1.4989x; 1.4989x over previous
#include <cuda_runtime.h>
#include <cuda_fp16.h>
#include <math.h>

#define DTSTEP 0.03125f

// Scratch: voxel-major half4 volume. B=2, D=128 -> 2*128^3 * 8B = 32 MiB.
#define VOLH_CAP (2 * 128 * 128 * 128)
__device__ uint2 g_volh[VOLH_CAP];

// ---------------------------------------------------------------------------
// Pass 1: permute [B,4,D,D,D] fp32 channel-major -> [B,D,D,D] half4 voxel-major
// Vectorized: each thread handles 4 consecutive voxels (float4 reads per
// channel, 2x uint4 writes).
// ---------------------------------------------------------------------------
__global__ void permute_half_kernel(const float4* __restrict__ vol, int B, int D3) {
    int i = blockIdx.x * blockDim.x + threadIdx.x;   // voxel-group (4 voxels)
    int groups_per_b = D3 >> 2;
    int n = B * groups_per_b;
    if (i >= n) return;
    int b = i / groups_per_b;
    int r4 = i - b * groups_per_b;

    // vol viewed as float4: channel c of batch b starts at b*D3 + c*(D3/4)
    const float4* base = vol + (size_t)b * D3 + r4;
    float4 ch0 = base[0];
    float4 ch1 = base[(size_t)groups_per_b];
    float4 ch2 = base[2 * (size_t)groups_per_b];
    float4 ch3 = base[3 * (size_t)groups_per_b];

    const float* c0 = &ch0.x; const float* c1 = &ch1.x;
    const float* c2 = &ch2.x; const float* c3 = &ch3.x;

    uint2 outv[4];
    #pragma unroll
    for (int j = 0; j < 4; ++j) {
        __half2 h01 = __floats2half2_rn(c0[j], c1[j]);
        __half2 h23 = __floats2half2_rn(c2[j], c3[j]);
        outv[j].x = *reinterpret_cast<unsigned*>(&h01);
        outv[j].y = *reinterpret_cast<unsigned*>(&h23);
    }
    uint4* o = reinterpret_cast<uint4*>(g_volh + (size_t)b * D3 + (size_t)r4 * 4);
    o[0] = make_uint4(outv[0].x, outv[0].y, outv[1].x, outv[1].y);
    o[1] = make_uint4(outv[2].x, outv[2].y, outv[3].x, outv[3].y);
}

// ---------------------------------------------------------------------------
// Helpers
// ---------------------------------------------------------------------------
struct Corners {
    uint2 c000, c001, c010, c011, c100, c101, c110, c111;
};

__device__ __forceinline__ Corners load_corners(const uint2* __restrict__ g,
                                                size_t base, int D, int D2) {
    Corners r;
    r.c000 = __ldg(g + base);
    r.c001 = __ldg(g + base + 1);
    r.c010 = __ldg(g + base + D);
    r.c011 = __ldg(g + base + D + 1);
    r.c100 = __ldg(g + base + D2);
    r.c101 = __ldg(g + base + D2 + 1);
    r.c110 = __ldg(g + base + D2 + D);
    r.c111 = __ldg(g + base + D2 + D + 1);
    return r;
}

__device__ __forceinline__ float4 h4tof4(uint2 u) {
    __half2 h01 = *reinterpret_cast<__half2*>(&u.x);
    __half2 h23 = *reinterpret_cast<__half2*>(&u.y);
    float2 f01 = __half22float2(h01);
    float2 f23 = __half22float2(h23);
    return make_float4(f01.x, f01.y, f23.x, f23.y);
}

__device__ __forceinline__ float4 lerp4(float4 a, float4 b, float t) {
    float s = 1.0f - t;
    return make_float4(a.x * s + b.x * t,
                       a.y * s + b.y * t,
                       a.z * s + b.z * t,
                       a.w * s + b.w * t);
}

__device__ __forceinline__ float4 trilerp(const Corners& c,
                                          float wx, float wy, float wz) {
    float4 a000 = h4tof4(c.c000), a001 = h4tof4(c.c001);
    float4 a010 = h4tof4(c.c010), a011 = h4tof4(c.c011);
    float4 a100 = h4tof4(c.c100), a101 = h4tof4(c.c101);
    float4 a110 = h4tof4(c.c110), a111 = h4tof4(c.c111);
    float4 c00 = lerp4(a000, a001, wx);
    float4 c01 = lerp4(a010, a011, wx);
    float4 c10 = lerp4(a100, a101, wx);
    float4 c11 = lerp4(a110, a111, wx);
    float4 c0 = lerp4(c00, c01, wy);
    float4 c1 = lerp4(c10, c11, wy);
    return lerp4(c0, c1, wz);
}

// ---------------------------------------------------------------------------
// Pass 2: one thread per pixel ray, software-pipelined corner loads.
// Ray setup uses IEEE RN intrinsics to bit-match XLA on the boundary-sensitive
// path (validity test). Interpolation uses fp16 volume (tolerance analysis:
// <=4.9e-4 relative per sample vs 1e-3 threshold).
// ---------------------------------------------------------------------------
__global__ void __launch_bounds__(128, 8)
raymarch_kernel(const float* __restrict__ camrot,
                const float* __restrict__ campos,
                const float* __restrict__ focal,
                const float* __restrict__ princpt,
                const float* __restrict__ pix,
                float* __restrict__ out,
                int B, int H, int W, int D, int nsteps) {
    int x = blockIdx.x * 32 + threadIdx.x;
    int y = blockIdx.y * 4 + threadIdx.y;
    int b = blockIdx.z;
    if (x >= W || y >= H) return;

    // --- camera ray (IEEE RN, matches XLA HLO op-by-op) ---
    float fx = focal[b * 2 + 0], fy = focal[b * 2 + 1];
    float px = princpt[b * 2 + 0], py = princpt[b * 2 + 1];
    size_t pidx = (((size_t)b * H + y) * W + x) * 2;
    float u = __fdiv_rn(__fsub_rn(pix[pidx + 0], px), fx);
    float v = __fdiv_rn(__fsub_rn(pix[pidx + 1], py), fy);

    const float* R = camrot + b * 9;
    float dx = __fadd_rn(__fadd_rn(__fmul_rn(R[0], u), __fmul_rn(R[3], v)), R[6]);
    float dy = __fadd_rn(__fadd_rn(__fmul_rn(R[1], u), __fmul_rn(R[4], v)), R[7]);
    float dz = __fadd_rn(__fadd_rn(__fmul_rn(R[2], u), __fmul_rn(R[5], v)), R[8]);

    float sxx = __fmul_rn(dx, dx);
    float syy = __fmul_rn(dy, dy);
    float szz = __fmul_rn(dz, dz);
    float norm = __fsqrt_rn(__fadd_rn(__fadd_rn(sxx, syy), szz));
    dx = __fdiv_rn(dx, norm);
    dy = __fdiv_rn(dy, norm);
    dz = __fdiv_rn(dz, norm);

    float cx = campos[b * 3 + 0], cy = campos[b * 3 + 1], cz = campos[b * 3 + 2];

    float t1x = __fdiv_rn(__fsub_rn(-1.0f, cx), dx);
    float t2x = __fdiv_rn(__fsub_rn( 1.0f, cx), dx);
    float t1y = __fdiv_rn(__fsub_rn(-1.0f, cy), dy);
    float t2y = __fdiv_rn(__fsub_rn( 1.0f, cy), dy);
    float t1z = __fdiv_rn(__fsub_rn(-1.0f, cz), dz);
    float t2z = __fdiv_rn(__fsub_rn( 1.0f, cz), dz);
    float tmin = fmaxf(fminf(t1x, t2x),
                 fmaxf(fminf(t1y, t2y), fminf(t1z, t2z)));
    float tmax = fminf(fmaxf(t1x, t2x),
                 fminf(fmaxf(t1y, t2y), fmaxf(t1z, t2z)));
    bool hit = tmin < tmax;

    size_t obase = ((size_t)b * 4) * H * W + (size_t)y * W + x;
    size_t cstr = (size_t)H * W;

    float r0 = 0.0f, r1 = 0.0f, r2 = 0.0f, alpha = 0.0f;

    if (hit) {
        float t0 = fmaxf(tmin, 0.0f);
        float posx = __fadd_rn(cx, __fmul_rn(dx, t0));
        float posy = __fadd_rn(cy, __fmul_rn(dy, t0));
        float posz = __fadd_rn(cz, __fmul_rn(dz, t0));
        float stepx = __fmul_rn(dx, DTSTEP);   // exact (DT = 2^-5)
        float stepy = __fmul_rn(dy, DTSTEP);
        float stepz = __fmul_rn(dz, DTSTEP);

        const float hiD = (float)(D - 1);
        const int D2 = D * D;
        const size_t vb = (size_t)b * D * D2;
        const uint2* g = g_volh;

        #define INSIDE ((posx > -1.0f) & (posx < 1.0f) & \
                        (posy > -1.0f) & (posy < 1.0f) & \
                        (posz > -1.0f) & (posz < 1.0f))

        // entry scan: advance until first valid sample (positions monotone per
        // axis, so the valid region is one contiguous interval of steps)
        int s = 0;
        bool valid = INSIDE;
        while (!valid && (s + 1) < nsteps) {
            posx = __fadd_rn(posx, stepx);
            posy = __fadd_rn(posy, stepy);
            posz = __fadd_rn(posz, stepz);
            ++s;
            valid = INSIDE;
        }

        if (valid) {
            // current-step index + weights + loads
            float gx = fminf(fmaxf(__fmul_rn(__fmul_rn(__fadd_rn(posx, 1.0f), 0.5f), hiD), 0.0f), hiD);
            float gy = fminf(fmaxf(__fmul_rn(__fmul_rn(__fadd_rn(posy, 1.0f), 0.5f), hiD), 0.0f), hiD);
            float gz = fminf(fmaxf(__fmul_rn(__fmul_rn(__fadd_rn(posz, 1.0f), 0.5f), hiD), 0.0f), hiD);
            int x0 = min((int)gx, D - 2);
            int y0 = min((int)gy, D - 2);
            int z0 = min((int)gz, D - 2);
            float cwx = gx - (float)x0, cwy = gy - (float)y0, cwz = gz - (float)z0;
            Corners cur = load_corners(g, vb + (size_t)z0 * D2 + (size_t)y0 * D + x0, D, D2);

            for (;;) {
                // advance + prefetch next step's corners BEFORE consuming cur
                posx = __fadd_rn(posx, stepx);
                posy = __fadd_rn(posy, stepy);
                posz = __fadd_rn(posz, stepz);
                ++s;
                bool vnext = (s < nsteps) && INSIDE;
                Corners nxt;
                float nwx = 0.0f, nwy = 0.0f, nwz = 0.0f;
                if (vnext) {
                    float ngx = fminf(fmaxf(__fmul_rn(__fmul_rn(__fadd_rn(posx, 1.0f), 0.5f), hiD), 0.0f), hiD);
                    float ngy = fminf(fmaxf(__fmul_rn(__fmul_rn(__fadd_rn(posy, 1.0f), 0.5f), hiD), 0.0f), hiD);
                    float ngz = fminf(fmaxf(__fmul_rn(__fmul_rn(__fadd_rn(posz, 1.0f), 0.5f), hiD), 0.0f), hiD);
                    int nx0 = min((int)ngx, D - 2);
                    int ny0 = min((int)ngy, D - 2);
                    int nz0 = min((int)ngz, D - 2);
                    nwx = ngx - (float)nx0; nwy = ngy - (float)ny0; nwz = ngz - (float)nz0;
                    nxt = load_corners(g, vb + (size_t)nz0 * D2 + (size_t)ny0 * D + nx0, D, D2);
                }

                // consume current step
                float4 smp = trilerp(cur, cwx, cwy, cwz);
                float contrib = fminf(alpha + smp.w * DTSTEP, 1.0f) - alpha;
                r0 += smp.x * contrib;
                r1 += smp.y * contrib;
                r2 += smp.z * contrib;
                alpha += contrib;

                // saturation: all remaining contribs sum to <= 1e-6 (absolute)
                if (!vnext || (1.0f - alpha < 1e-6f)) break;
                cur = nxt; cwx = nwx; cwy = nwy; cwz = nwz;
            }
        }
        #undef INSIDE
    }

    out[obase + 0 * cstr] = r0;
    out[obase + 1 * cstr] = r1;
    out[obase + 2 * cstr] = r2;
    out[obase + 3 * cstr] = alpha;
}

// ---------------------------------------------------------------------------
// Launch
// ---------------------------------------------------------------------------
extern "C" void kernel_launch(void* const* d_in, const int* in_sizes, int n_in,
                              void* d_out, int out_size) {
    const float* camrot  = (const float*)d_in[0];
    const float* campos  = (const float*)d_in[1];
    const float* focal   = (const float*)d_in[2];
    const float* princpt = (const float*)d_in[3];
    const float* pix     = (const float*)d_in[4];
    const float* volume  = (const float*)d_in[5];
    float* out = (float*)d_out;

    int B = in_sizes[1] / 3;
    int hw = in_sizes[4] / (2 * B);
    int H = (int)(sqrt((double)hw) + 0.5);
    int W = H;
    int d3 = in_sizes[5] / (4 * B);
    int D = (int)(cbrt((double)d3) + 0.5);
    int nsteps = (int)ceil(2.0 * sqrt(3.0) / 0.03125);  // 111

    int ngroups = B * (d3 / 4);
    permute_half_kernel<<<(ngroups + 255) / 256, 256>>>(
        (const float4*)volume, B, d3);

    dim3 block(32, 4, 1);
    dim3 grid((W + 31) / 32, (H + 3) / 4, B);
    raymarch_kernel<<<grid, block>>>(camrot, campos, focal, princpt, pix,
                                     out, B, H, W, D, nsteps);
}

// round 12
// speedup vs baseline: 1.8666x; 1.2453x over previous
#include <cuda_runtime.h>
#include <cuda_fp16.h>
#include <math.h>

#define DTSTEP 0.03125f

// Scratch: voxel-major half4 volume. B=2, D=128 -> 2*128^3 * 8B = 32 MiB.
#define VOLH_CAP (2 * 128 * 128 * 128)
__device__ uint2 g_volh[VOLH_CAP];

// ---------------------------------------------------------------------------
// Pass 1: permute [B,4,D,D,D] fp32 channel-major -> [B,D,D,D] half4 voxel-major
// ---------------------------------------------------------------------------
__global__ void permute_half_kernel(const float4* __restrict__ vol, int B, int D3) {
    int i = blockIdx.x * blockDim.x + threadIdx.x;   // voxel-group (4 voxels)
    int groups_per_b = D3 >> 2;
    int n = B * groups_per_b;
    if (i >= n) return;
    int b = i / groups_per_b;
    int r4 = i - b * groups_per_b;

    const float4* base = vol + (size_t)b * D3 + r4;
    float4 ch0 = base[0];
    float4 ch1 = base[(size_t)groups_per_b];
    float4 ch2 = base[2 * (size_t)groups_per_b];
    float4 ch3 = base[3 * (size_t)groups_per_b];

    const float* c0 = &ch0.x; const float* c1 = &ch1.x;
    const float* c2 = &ch2.x; const float* c3 = &ch3.x;

    uint2 outv[4];
    #pragma unroll
    for (int j = 0; j < 4; ++j) {
        __half2 h01 = __floats2half2_rn(c0[j], c1[j]);
        __half2 h23 = __floats2half2_rn(c2[j], c3[j]);
        outv[j].x = *reinterpret_cast<unsigned*>(&h01);
        outv[j].y = *reinterpret_cast<unsigned*>(&h23);
    }
    uint4* o = reinterpret_cast<uint4*>(g_volh + (size_t)b * D3 + (size_t)r4 * 4);
    o[0] = make_uint4(outv[0].x, outv[0].y, outv[1].x, outv[1].y);
    o[1] = make_uint4(outv[2].x, outv[2].y, outv[3].x, outv[3].y);
}

// ---------------------------------------------------------------------------
// Helpers
// ---------------------------------------------------------------------------
struct Corners {
    uint2 c000, c001, c010, c011, c100, c101, c110, c111;
};

__device__ __forceinline__ Corners load_corners(const uint2* __restrict__ g,
                                                int base, int D, int D2) {
    Corners r;
    r.c000 = __ldg(g + base);
    r.c001 = __ldg(g + base + 1);
    r.c010 = __ldg(g + base + D);
    r.c011 = __ldg(g + base + D + 1);
    r.c100 = __ldg(g + base + D2);
    r.c101 = __ldg(g + base + D2 + 1);
    r.c110 = __ldg(g + base + D2 + D);
    r.c111 = __ldg(g + base + D2 + D + 1);
    return r;
}

struct H4 { __half2 lo, hi; };  // lo = channels 0,1; hi = channels 2,3

__device__ __forceinline__ H4 u2h4(uint2 u) {
    H4 r;
    r.lo = *reinterpret_cast<__half2*>(&u.x);
    r.hi = *reinterpret_cast<__half2*>(&u.y);
    return r;
}

// lerp: a + t*(b-a) in packed half2, both lanes
__device__ __forceinline__ H4 lerpH(H4 a, H4 b, __half2 t) {
    H4 r;
    r.lo = __hfma2(t, __hsub2(b.lo, a.lo), a.lo);
    r.hi = __hfma2(t, __hsub2(b.hi, a.hi), a.hi);
    return r;
}

// full trilinear in half2; only the final value converts to fp32
__device__ __forceinline__ float4 trilerp(const Corners& c,
                                          float wx, float wy, float wz) {
    __half2 tx = __float2half2_rn(wx);
    __half2 ty = __float2half2_rn(wy);
    __half2 tz = __float2half2_rn(wz);
    H4 c00 = lerpH(u2h4(c.c000), u2h4(c.c001), tx);
    H4 c01 = lerpH(u2h4(c.c010), u2h4(c.c011), tx);
    H4 c10 = lerpH(u2h4(c.c100), u2h4(c.c101), tx);
    H4 c11 = lerpH(u2h4(c.c110), u2h4(c.c111), tx);
    H4 c0 = lerpH(c00, c01, ty);
    H4 c1 = lerpH(c10, c11, ty);
    H4 r  = lerpH(c0, c1, tz);
    float2 f01 = __half22float2(r.lo);
    float2 f23 = __half22float2(r.hi);
    return make_float4(f01.x, f01.y, f23.x, f23.y);
}

// ---------------------------------------------------------------------------
// Pass 2: one thread per pixel ray, software-pipelined corner loads.
// Ray setup + validity test use IEEE RN intrinsics (bit-match XLA on the
// boundary decision). Interpolation runs in packed half2 (weights are not
// boundary-sensitive: trilinear interp is continuous across cell boundaries).
// ---------------------------------------------------------------------------
__global__ void __launch_bounds__(128, 8)
raymarch_kernel(const float* __restrict__ camrot,
                const float* __restrict__ campos,
                const float* __restrict__ focal,
                const float* __restrict__ princpt,
                const float* __restrict__ pix,
                float* __restrict__ out,
                int B, int H, int W, int D, int nsteps) {
    int x = blockIdx.x * 32 + threadIdx.x;
    int y = blockIdx.y * 4 + threadIdx.y;
    int b = blockIdx.z;
    if (x >= W || y >= H) return;

    // --- camera ray (IEEE RN, matches XLA HLO op-by-op) ---
    float fx = focal[b * 2 + 0], fy = focal[b * 2 + 1];
    float px = princpt[b * 2 + 0], py = princpt[b * 2 + 1];
    size_t pidx = (((size_t)b * H + y) * W + x) * 2;
    float u = __fdiv_rn(__fsub_rn(pix[pidx + 0], px), fx);
    float v = __fdiv_rn(__fsub_rn(pix[pidx + 1], py), fy);

    const float* R = camrot + b * 9;
    float dx = __fadd_rn(__fadd_rn(__fmul_rn(R[0], u), __fmul_rn(R[3], v)), R[6]);
    float dy = __fadd_rn(__fadd_rn(__fmul_rn(R[1], u), __fmul_rn(R[4], v)), R[7]);
    float dz = __fadd_rn(__fadd_rn(__fmul_rn(R[2], u), __fmul_rn(R[5], v)), R[8]);

    float sxx = __fmul_rn(dx, dx);
    float syy = __fmul_rn(dy, dy);
    float szz = __fmul_rn(dz, dz);
    float norm = __fsqrt_rn(__fadd_rn(__fadd_rn(sxx, syy), szz));
    dx = __fdiv_rn(dx, norm);
    dy = __fdiv_rn(dy, norm);
    dz = __fdiv_rn(dz, norm);

    float cx = campos[b * 3 + 0], cy = campos[b * 3 + 1], cz = campos[b * 3 + 2];

    float t1x = __fdiv_rn(__fsub_rn(-1.0f, cx), dx);
    float t2x = __fdiv_rn(__fsub_rn( 1.0f, cx), dx);
    float t1y = __fdiv_rn(__fsub_rn(-1.0f, cy), dy);
    float t2y = __fdiv_rn(__fsub_rn( 1.0f, cy), dy);
    float t1z = __fdiv_rn(__fsub_rn(-1.0f, cz), dz);
    float t2z = __fdiv_rn(__fsub_rn( 1.0f, cz), dz);
    float tmin = fmaxf(fminf(t1x, t2x),
                 fmaxf(fminf(t1y, t2y), fminf(t1z, t2z)));
    float tmax = fminf(fmaxf(t1x, t2x),
                 fminf(fmaxf(t1y, t2y), fmaxf(t1z, t2z)));
    bool hit = tmin < tmax;

    size_t obase = ((size_t)b * 4) * H * W + (size_t)y * W + x;
    size_t cstr = (size_t)H * W;

    float r0 = 0.0f, r1 = 0.0f, r2 = 0.0f, alpha = 0.0f;

    if (hit) {
        float t0 = fmaxf(tmin, 0.0f);
        float posx = __fadd_rn(cx, __fmul_rn(dx, t0));
        float posy = __fadd_rn(cy, __fmul_rn(dy, t0));
        float posz = __fadd_rn(cz, __fmul_rn(dz, t0));
        float stepx = __fmul_rn(dx, DTSTEP);   // exact (DT = 2^-5)
        float stepy = __fmul_rn(dy, DTSTEP);
        float stepz = __fmul_rn(dz, DTSTEP);

        const float scaleD = 0.5f * (float)(D - 1);   // folded (pos+1)*0.5*(D-1)
        const int D2 = D * D;
        const int vb = b * D * D2;                    // < 2^22, int is safe
        const uint2* g = g_volh;

        #define INSIDE ((posx > -1.0f) & (posx < 1.0f) & \
                        (posy > -1.0f) & (posy < 1.0f) & \
                        (posz > -1.0f) & (posz < 1.0f))

        // entry scan: positions monotone per axis -> valid region contiguous
        int s = 0;
        bool valid = INSIDE;
        while (!valid && (s + 1) < nsteps) {
            posx = __fadd_rn(posx, stepx);
            posy = __fadd_rn(posy, stepy);
            posz = __fadd_rn(posz, stepz);
            ++s;
            valid = INSIDE;
        }

        if (valid) {
            // inside the box, (pos+1)*scaleD lands in [0, D-1] after rounding,
            // so no clip needed; min(.,D-2) still guards the +1 corner.
            float gx = (posx + 1.0f) * scaleD;
            float gy = (posy + 1.0f) * scaleD;
            float gz = (posz + 1.0f) * scaleD;
            int x0 = min((int)gx, D - 2);
            int y0 = min((int)gy, D - 2);
            int z0 = min((int)gz, D - 2);
            float cwx = gx - (float)x0, cwy = gy - (float)y0, cwz = gz - (float)z0;
            Corners cur = load_corners(g, vb + z0 * D2 + y0 * D + x0, D, D2);

            for (;;) {
                // advance + prefetch next step's corners BEFORE consuming cur
                posx = __fadd_rn(posx, stepx);
                posy = __fadd_rn(posy, stepy);
                posz = __fadd_rn(posz, stepz);
                ++s;
                bool vnext = (s < nsteps) && INSIDE;
                Corners nxt;
                float nwx = 0.0f, nwy = 0.0f, nwz = 0.0f;
                if (vnext) {
                    float ngx = (posx + 1.0f) * scaleD;
                    float ngy = (posy + 1.0f) * scaleD;
                    float ngz = (posz + 1.0f) * scaleD;
                    int nx0 = min((int)ngx, D - 2);
                    int ny0 = min((int)ngy, D - 2);
                    int nz0 = min((int)ngz, D - 2);
                    nwx = ngx - (float)nx0; nwy = ngy - (float)ny0; nwz = ngz - (float)nz0;
                    nxt = load_corners(g, vb + nz0 * D2 + ny0 * D + nx0, D, D2);
                }

                // consume current step (half2 lerp tree, fp32 composite)
                float4 smp = trilerp(cur, cwx, cwy, cwz);
                float contrib = fminf(alpha + smp.w * DTSTEP, 1.0f) - alpha;
                r0 += smp.x * contrib;
                r1 += smp.y * contrib;
                r2 += smp.z * contrib;
                alpha += contrib;

                // saturation: all remaining contribs sum to <= 1e-6 (absolute)
                if (!vnext || (1.0f - alpha < 1e-6f)) break;
                cur = nxt; cwx = nwx; cwy = nwy; cwz = nwz;
            }
        }
        #undef INSIDE
    }

    out[obase + 0 * cstr] = r0;
    out[obase + 1 * cstr] = r1;
    out[obase + 2 * cstr] = r2;
    out[obase + 3 * cstr] = alpha;
}

// ---------------------------------------------------------------------------
// Launch
// ---------------------------------------------------------------------------
extern "C" void kernel_launch(void* const* d_in, const int* in_sizes, int n_in,
                              void* d_out, int out_size) {
    const float* camrot  = (const float*)d_in[0];
    const float* campos  = (const float*)d_in[1];
    const float* focal   = (const float*)d_in[2];
    const float* princpt = (const float*)d_in[3];
    const float* pix     = (const float*)d_in[4];
    const float* volume  = (const float*)d_in[5];
    float* out = (float*)d_out;

    int B = in_sizes[1] / 3;
    int hw = in_sizes[4] / (2 * B);
    int H = (int)(sqrt((double)hw) + 0.5);
    int W = H;
    int d3 = in_sizes[5] / (4 * B);
    int D = (int)(cbrt((double)d3) + 0.5);
    int nsteps = (int)ceil(2.0 * sqrt(3.0) / 0.03125);  // 111

    int ngroups = B * (d3 / 4);
    permute_half_kernel<<<(ngroups + 255) / 256, 256>>>(
        (const float4*)volume, B, d3);

    dim3 block(32, 4, 1);
    dim3 grid((W + 31) / 32, (H + 3) / 4, B);
    raymarch_kernel<<<grid, block>>>(camrot, campos, focal, princpt, pix,
                                     out, B, H, W, D, nsteps);
}